// round 5
// baseline (speedup 1.0000x reference)
#include <cuda_runtime.h>
#include <cuda_bf16.h>
#include <stdint.h>

#define S_REAL   308
#define SP       320     // padded state count
#define E_DIM    126
#define T_LEN    4096
#define NBATCH   32
#define NIP      160     // SP/2 pair-words of alpha
#define HSPLIT   4
#define SCAN_THREADS 320
#define KK       40      // i-pairs per h-slice per thread

// Scratch (device globals — no allocation in kernel_launch)
__device__ __nv_bfloat16 g_emis[(size_t)NBATCH * T_LEN * SP];   // 80 MB
__device__ uint32_t      g_apk[NIP * SP];                        // packed A, 200 KB

__device__ __forceinline__ __nv_bfloat162 u32_bf2(uint32_t v) {
    return *reinterpret_cast<__nv_bfloat162*>(&v);
}
__device__ __forceinline__ uint32_t bf2_u32(__nv_bfloat162 v) {
    return *reinterpret_cast<uint32_t*>(&v);
}
__device__ __forceinline__ uint32_t smem_u32(const void* p) {
    uint32_t a;
    asm("{ .reg .u64 t; cvta.to.shared.u64 t, %1; cvt.u32.u64 %0, t; }"
        : "=r"(a) : "l"(p));
    return a;
}
__device__ __forceinline__ void mbar_init(uint32_t addr, uint32_t count) {
    asm volatile("mbarrier.init.shared.b64 [%0], %1;" :: "r"(addr), "r"(count) : "memory");
}
__device__ __forceinline__ void mbar_arrive_own(uint32_t addr) {
    asm volatile("mbarrier.arrive.release.cluster.shared::cta.b64 _, [%0];"
                 :: "r"(addr) : "memory");
}
__device__ __forceinline__ void mbar_arrive_peer(uint32_t addr, uint32_t peer) {
    asm volatile("{ .reg .b32 r; mapa.shared::cluster.u32 r, %0, %1;"
                 " mbarrier.arrive.release.cluster.shared::cluster.b64 _, [r]; }"
                 :: "r"(addr), "r"(peer) : "memory");
}
__device__ __forceinline__ void st_peer_u32(uint32_t addr, uint32_t peer, uint32_t val) {
    asm volatile("{ .reg .b32 r; mapa.shared::cluster.u32 r, %0, %1;"
                 " st.shared::cluster.u32 [r], %2; }"
                 :: "r"(addr), "r"(peer), "r"(val) : "memory");
}
__device__ __forceinline__ void mbar_wait_parity(uint32_t addr, uint32_t parity) {
    asm volatile(
        "{ .reg .pred P;\n\t"
        "WAIT_%=:\n\t"
        "mbarrier.try_wait.parity.acquire.cluster.shared::cta.b64 P, [%0], %1, 0x989680;\n\t"
        "@P bra DONE_%=;\n\t"
        "bra WAIT_%=;\n\t"
        "DONE_%=: }"
        :: "r"(addr), "r"(parity) : "memory");
}
#define CLUSTER_SYNC() do { \
    asm volatile("barrier.cluster.arrive.aligned;" ::: "memory"); \
    asm volatile("barrier.cluster.wait.aligned;" ::: "memory"); \
} while (0)

// ---------------------------------------------------------------------------
// Pack A (fp32 [308][308]) into bf16x2 words.
// Word for (ip, j): lo = A[2ip][j], hi = A[2ip+1][j], zero-padded to 320x320.
// Quad (ip*80+jg) holds j = jg + 80q for q = 0..3 at .x.y.z.w.
// CTA rank r of a cluster reads the uint2 {q=2r, q=2r+1} of each quad.
// ---------------------------------------------------------------------------
__global__ void prep_apk_kernel(const float* __restrict__ A) {
    int idx = blockIdx.x * blockDim.x + threadIdx.x;
    if (idx >= NIP * SP) return;
    int ip = idx / SP;
    int j  = idx - ip * SP;
    int i0 = 2 * ip, i1 = i0 + 1;
    float a0 = (i0 < S_REAL && j < S_REAL) ? A[i0 * S_REAL + j] : 0.f;
    float a1 = (i1 < S_REAL && j < S_REAL) ? A[i1 * S_REAL + j] : 0.f;
    __nv_bfloat162 w = __floats2bfloat162_rn(a0, a1);
    int jg = j % 80, q = j / 80;
    g_apk[(ip * 80 + jg) * 4 + q] = bf2_u32(w);
}

// ---------------------------------------------------------------------------
// Emission GEMM (bf16x2 / HFMA2): emis[m][n] = sum_e inputs[m][e] * B[n][e]
// ---------------------------------------------------------------------------
__global__ void __launch_bounds__(256)
emis_gemm_kernel(const float* __restrict__ inp, const float* __restrict__ Bm) {
    __shared__ uint32_t sAp[64][16];
    __shared__ uint32_t sBp[16][64];

    const int tid = threadIdx.x;
    const int tx = tid & 15;
    const int ty = tid >> 4;
    const int n0 = blockIdx.x * 64;
    const int m0 = blockIdx.y * 64;

    float acc[4][4];
#pragma unroll
    for (int u = 0; u < 4; ++u)
#pragma unroll
        for (int v = 0; v < 4; ++v) acc[u][v] = 0.f;

    const __nv_bfloat162 zero2 = __floats2bfloat162_rn(0.f, 0.f);

    for (int k0 = 0; k0 < 128; k0 += 32) {
#pragma unroll
        for (int r = 0; r < 4; ++r) {
            int lin = tid + r * 256;
            int mm = lin >> 4, kp = lin & 15;
            int k = k0 + 2 * kp;
            __nv_bfloat162 w = zero2;
            if (k < E_DIM) {
                float2 f = *reinterpret_cast<const float2*>(
                    &inp[(size_t)(m0 + mm) * E_DIM + k]);
                w = __floats2bfloat162_rn(f.x, f.y);
            }
            sAp[mm][kp] = bf2_u32(w);
        }
#pragma unroll
        for (int r = 0; r < 4; ++r) {
            int lin = tid + r * 256;
            int kp = lin >> 6, n = lin & 63;
            int k = k0 + 2 * kp;
            int nn = n0 + n;
            __nv_bfloat162 w = zero2;
            if (k < E_DIM && nn < S_REAL) {
                float2 f = *reinterpret_cast<const float2*>(
                    &Bm[(size_t)nn * E_DIM + k]);
                w = __floats2bfloat162_rn(f.x, f.y);
            }
            sBp[kp][n] = bf2_u32(w);
        }
        __syncthreads();

        __nv_bfloat162 acc2[4][4];
#pragma unroll
        for (int u = 0; u < 4; ++u)
#pragma unroll
            for (int v = 0; v < 4; ++v) acc2[u][v] = zero2;

#pragma unroll
        for (int kp = 0; kp < 16; ++kp) {
            uint4 bv = *reinterpret_cast<const uint4*>(&sBp[kp][tx * 4]);
            uint32_t a0 = sAp[ty * 4 + 0][kp];
            uint32_t a1 = sAp[ty * 4 + 1][kp];
            uint32_t a2 = sAp[ty * 4 + 2][kp];
            uint32_t a3 = sAp[ty * 4 + 3][kp];
            __nv_bfloat162 b0 = u32_bf2(bv.x), b1 = u32_bf2(bv.y);
            __nv_bfloat162 b2 = u32_bf2(bv.z), b3 = u32_bf2(bv.w);
            acc2[0][0] = __hfma2(u32_bf2(a0), b0, acc2[0][0]);
            acc2[0][1] = __hfma2(u32_bf2(a0), b1, acc2[0][1]);
            acc2[0][2] = __hfma2(u32_bf2(a0), b2, acc2[0][2]);
            acc2[0][3] = __hfma2(u32_bf2(a0), b3, acc2[0][3]);
            acc2[1][0] = __hfma2(u32_bf2(a1), b0, acc2[1][0]);
            acc2[1][1] = __hfma2(u32_bf2(a1), b1, acc2[1][1]);
            acc2[1][2] = __hfma2(u32_bf2(a1), b2, acc2[1][2]);
            acc2[1][3] = __hfma2(u32_bf2(a1), b3, acc2[1][3]);
            acc2[2][0] = __hfma2(u32_bf2(a2), b0, acc2[2][0]);
            acc2[2][1] = __hfma2(u32_bf2(a2), b1, acc2[2][1]);
            acc2[2][2] = __hfma2(u32_bf2(a2), b2, acc2[2][2]);
            acc2[2][3] = __hfma2(u32_bf2(a2), b3, acc2[2][3]);
            acc2[3][0] = __hfma2(u32_bf2(a3), b0, acc2[3][0]);
            acc2[3][1] = __hfma2(u32_bf2(a3), b1, acc2[3][1]);
            acc2[3][2] = __hfma2(u32_bf2(a3), b2, acc2[3][2]);
            acc2[3][3] = __hfma2(u32_bf2(a3), b3, acc2[3][3]);
        }
#pragma unroll
        for (int u = 0; u < 4; ++u)
#pragma unroll
            for (int v = 0; v < 4; ++v) {
                float2 p = __bfloat1622float2(acc2[u][v]);
                acc[u][v] += p.x + p.y;
            }
        __syncthreads();
    }
#pragma unroll
    for (int u = 0; u < 4; ++u) {
        int m = m0 + ty * 4 + u;
        size_t base = (size_t)m * SP + n0 + tx * 4;
#pragma unroll
        for (int v = 0; v < 4; v += 2) {
            __nv_bfloat162 p = __floats2bfloat162_rn(acc[u][v], acc[u][v + 1]);
            *reinterpret_cast<uint32_t*>(&g_emis[base + v]) = bf2_u32(p);
        }
    }
}

// ---------------------------------------------------------------------------
// Scan: 2-CTA cluster per batch. CTA rank r computes alpha_new[j] for the 160
// j's with q in {2r, 2r+1} (j = jg + 80q). A fully register-resident (40 uint2
// per thread). Per step: fma -> __syncthreads -> o = reduce*e -> pack bf16x2
// pairs -> write own smem + peer DSMEM -> mbarrier (160 arrivals, cluster
// release/acquire) -> wait. Alpha double-buffered. Renorm every 8 steps with a
// 2-count mbarrier exchanging per-CTA partial z (log telescoped).
// ---------------------------------------------------------------------------
__global__ void __launch_bounds__(SCAN_THREADS, 1) __cluster_dims__(2, 1, 1)
scan_kernel(const float* __restrict__ Ivec, float* __restrict__ out) {
    __shared__ uint32_t s_alpha[2][NIP];       // full alpha (both halves), 2 buffers
    __shared__ float    s_red[HSPLIT][160];
    __shared__ float    s_outf[160];
    __shared__ float    s_zpart[2];
    __shared__ uint64_t s_bar_alpha;
    __shared__ uint64_t s_bar_norm;

    const int tid = threadIdx.x;
    const int h   = tid / 80;                  // 0..3  (40 i-pairs each)
    const int jg  = tid - h * 80;              // 0..79
    uint32_t rank;
    asm("mov.u32 %0, %%cluster_ctarank;" : "=r"(rank));
    const uint32_t peer = rank ^ 1u;
    const int b = blockIdx.x >> 1;

    const uint32_t bar_alpha_a = smem_u32(&s_bar_alpha);
    const uint32_t bar_norm_a  = smem_u32(&s_bar_norm);

    if (tid == 0) {
        mbar_init(bar_alpha_a, 160);           // 80 local + 80 peer writers
        mbar_init(bar_norm_a, 2);              // local tid0 + peer tid0
    }
    __syncthreads();
    CLUSTER_SYNC();                            // mbarrier visibility before DSMEM use

    const __nv_bfloat16* erow = g_emis + (size_t)b * T_LEN * SP;

    // register-resident A slice: uint2 {q=2r, q=2r+1} of quads (h*KK+kk)*80+jg
    uint2 rA[KK];
    {
        const uint2* Ap2 = reinterpret_cast<const uint2*>(g_apk);
#pragma unroll
        for (int kk = 0; kk < KK; ++kk)
            rA[kk] = Ap2[(size_t)((h * KK + kk) * 80 + jg) * 2 + rank];
    }

    // t = 0 init: both CTAs fill full alpha locally into buffer 1 (t=1 reads buf 1)
    if (tid < NIP) {
        int j0 = 2 * tid, j1 = j0 + 1;
        float e0 = __bfloat162float(erow[j0]);
        float e1 = __bfloat162float(erow[j1]);
        float w0 = (j0 < S_REAL) ? Ivec[j0] : 0.f;
        float w1 = (j1 < S_REAL) ? Ivec[j1] : 0.f;
        s_alpha[1][tid] = bf2_u32(__floats2bfloat162_rn(w0 * e0, w1 * e1));
    }
    __syncthreads();

    float ll = 0.f;
    uint32_t ap = 0, np = 0;

    float e_cur = 0.f;
    if (tid < 160)
        e_cur = __bfloat162float(erow[(size_t)SP + 160 * rank + tid]);

    const __nv_bfloat162 zero2 = __floats2bfloat162_rn(0.f, 0.f);

    for (int t = 1; t < T_LEN; ++t) {
        const int cur = t & 1;
        float e_next = 0.f;
        if (t + 1 < T_LEN && tid < 160)
            e_next = __bfloat162float(erow[(size_t)(t + 1) * SP + 160 * rank + tid]);

        // fma phase: 40 i-pairs x 2 j's
        __nv_bfloat162 a0 = zero2, a1 = zero2;
        const uint4* al4 = reinterpret_cast<const uint4*>(s_alpha[cur]);
#pragma unroll
        for (int c = 0; c < 2; ++c) {
            uint4 av[5];
#pragma unroll
            for (int r = 0; r < 5; ++r) av[r] = al4[h * 10 + c * 5 + r];
            const uint32_t* aw = reinterpret_cast<const uint32_t*>(av);
#pragma unroll
            for (int k = 0; k < 20; ++k) {
                uint2 w = rA[c * 20 + k];
                __nv_bfloat162 al = u32_bf2(aw[k]);
                a0 = __hfma2(u32_bf2(w.x), al, a0);
                a1 = __hfma2(u32_bf2(w.y), al, a1);
            }
        }
        float2 p0 = __bfloat1622float2(a0);
        float2 p1 = __bfloat1622float2(a1);
        s_red[h][jg]      = p0.x + p0.y;
        s_red[h][jg + 80] = p1.x + p1.y;
        __syncthreads();

        float o = 0.f;
        if (tid < 160)
            o = ((s_red[0][tid] + s_red[1][tid]) +
                 (s_red[2][tid] + s_red[3][tid])) * e_cur;

        if ((t & 7) == 7) {
            // global z across the cluster, renormalize, accumulate loglik
            if (tid < 160) s_outf[tid] = o;
            __syncthreads();
            if (tid < 32) {
                float s = 0.f;
#pragma unroll
                for (int k = 0; k < 5; ++k) s += s_outf[tid * 5 + k];
#pragma unroll
                for (int off = 16; off > 0; off >>= 1)
                    s += __shfl_xor_sync(0xffffffffu, s, off);
                if (tid == 0) {
                    s_zpart[rank] = s;
                    st_peer_u32(smem_u32(&s_zpart[rank]), peer, __float_as_uint(s));
                    mbar_arrive_own(bar_norm_a);
                    mbar_arrive_peer(bar_norm_a, peer);
                }
            }
            mbar_wait_parity(bar_norm_a, np); np ^= 1u;
            float z = s_zpart[0] + s_zpart[1];
            if (rank == 0 && tid == 0) ll += logf(z);
            if (tid < 160) o *= (1.0f / z);
        }

        // pack bf16 pairs, write own + peer alpha buffer, signal
        if (tid < 160) {
            float op = __shfl_down_sync(0xffffffffu, o, 1);
            if ((tid & 1) == 0) {
                uint32_t word = bf2_u32(__floats2bfloat162_rn(o, op));
                int widx = (tid >> 1) + 80 * (int)rank;
                uint32_t addr = smem_u32(&s_alpha[cur ^ 1][widx]);
                s_alpha[cur ^ 1][widx] = word;
                st_peer_u32(addr, peer, word);
                mbar_arrive_own(bar_alpha_a);
                mbar_arrive_peer(bar_alpha_a, peer);
            }
        }
        mbar_wait_parity(bar_alpha_a, ap); ap ^= 1u;

        e_cur = e_next;
    }

    if (rank == 0 && tid == 0) out[b] = ll;    // T_LEN % 8 == 0 -> ll complete
    CLUSTER_SYNC();                            // no exit with inbound DSMEM in flight
}

// ---------------------------------------------------------------------------
extern "C" void kernel_launch(void* const* d_in, const int* in_sizes, int n_in,
                              void* d_out, int out_size) {
    const float* inputs = nullptr;
    const float* A      = nullptr;
    const float* Bm     = nullptr;
    const float* Ivec   = nullptr;
    for (int i = 0; i < n_in; ++i) {
        switch (in_sizes[i]) {
            case NBATCH * T_LEN * E_DIM: inputs = (const float*)d_in[i]; break;
            case S_REAL * S_REAL:        A      = (const float*)d_in[i]; break;
            case S_REAL * E_DIM:         Bm     = (const float*)d_in[i]; break;
            case S_REAL:                 Ivec   = (const float*)d_in[i]; break;
            default: break;
        }
    }
    if (!inputs) inputs = (const float*)d_in[0];
    if (!A)      A      = (const float*)d_in[1];
    if (!Bm)     Bm     = (const float*)d_in[2];
    if (!Ivec)   Ivec   = (const float*)d_in[3];
    float* out = (float*)d_out;

    prep_apk_kernel<<<(NIP * SP + 255) / 256, 256>>>(A);

    dim3 ggrid(SP / 64, (NBATCH * T_LEN) / 64);   // (5, 2048)
    emis_gemm_kernel<<<ggrid, 256>>>(inputs, Bm);

    scan_kernel<<<NBATCH * 2, SCAN_THREADS>>>(Ivec, out);
    (void)out_size;
}